// round 1
// baseline (speedup 1.0000x reference)
#include <cuda_runtime.h>

// ---------------------------------------------------------------------------
// Scratch (device globals — no runtime allocation allowed)
// ---------------------------------------------------------------------------
#define N0MAX 500000
__device__ float g_x0[N0MAX * 16];
__device__ float g_c0[N0MAX * 16];
__device__ float g_x1[N0MAX * 16];
__device__ float g_c1[N0MAX * 16];
__device__ float g_x2[N0MAX * 16];
__device__ float g_c2[N0MAX * 16];
__device__ float g_stats[96];   // sum[0..47], sumsq[48..95]
__device__ float g_scale[48];
__device__ float g_shift[48];

#define EPS 1e-4f

// ---------------------------------------------------------------------------
// Zero BN stats
// ---------------------------------------------------------------------------
__global__ void zero_stats_kernel() {
    int t = threadIdx.x;
    if (t < 96) g_stats[t] = 0.0f;
}

// ---------------------------------------------------------------------------
// p1: submanifold conv, Cin=2 -> Cout=16, K=27, no input BN.
// nbr layout: [27, N], sentinel == N (== Nin == Nout here).
// ---------------------------------------------------------------------------
__global__ void sconv_p1_kernel(const float* __restrict__ feats,
                                const int* __restrict__ nbr,
                                const float* __restrict__ W,   // [27,2,16]
                                float* __restrict__ out, int N) {
    __shared__ float Ws[27 * 32];
    for (int t = threadIdx.x; t < 27 * 32; t += blockDim.x) Ws[t] = W[t];
    __syncthreads();
    int i = blockIdx.x * blockDim.x + threadIdx.x;
    if (i >= N) return;
    float acc[16];
#pragma unroll
    for (int c = 0; c < 16; c++) acc[c] = 0.0f;
    for (int k = 0; k < 27; k++) {
        int idx = __ldg(nbr + (size_t)k * N + i);
        if (idx < N) {
            float f0 = __ldg(feats + 2 * (size_t)idx);
            float f1 = __ldg(feats + 2 * (size_t)idx + 1);
            const float* w = Ws + k * 32;
#pragma unroll
            for (int c = 0; c < 16; c++)
                acc[c] = fmaf(f0, w[c], fmaf(f1, w[16 + c], acc[c]));
        }
    }
    float4* o = (float4*)(out + (size_t)i * 16);
#pragma unroll
    for (int q = 0; q < 4; q++)
        o[q] = make_float4(acc[4 * q], acc[4 * q + 1], acc[4 * q + 2], acc[4 * q + 3]);
}

// ---------------------------------------------------------------------------
// Generic 16->16 sparse conv with fused input BN-ReLU (scale/shift in
// g_scale/g_shift[0..15]) and optional residual add. K = 27 or 8.
// nbr: [K, Nout] indices into [0, Nin], sentinel == Nin.
// ---------------------------------------------------------------------------
__global__ void sconv16_kernel(const float* __restrict__ xin,
                               const int* __restrict__ nbr,
                               const float* __restrict__ W,     // [K,16,16]
                               const float* __restrict__ resid, // may be null
                               float* __restrict__ out,
                               int K, int Nout, int Nin) {
    extern __shared__ float smem[];
    float* Ws = smem;                 // K*256
    for (int t = threadIdx.x; t < K * 256; t += blockDim.x) Ws[t] = W[t];
    __syncthreads();

    float rs[16], rh[16];
#pragma unroll
    for (int c = 0; c < 16; c++) { rs[c] = g_scale[c]; rh[c] = g_shift[c]; }

    int i = blockIdx.x * blockDim.x + threadIdx.x;
    if (i >= Nout) return;

    float acc[16];
#pragma unroll
    for (int c = 0; c < 16; c++) acc[c] = 0.0f;

    for (int k = 0; k < K; k++) {
        int idx = __ldg(nbr + (size_t)k * Nout + i);
        if (idx < Nin) {
            const float4* xr = (const float4*)(xin + (size_t)idx * 16);
            float4 a = __ldg(xr + 0);
            float4 b = __ldg(xr + 1);
            float4 c4 = __ldg(xr + 2);
            float4 d = __ldg(xr + 3);
            float xv[16] = {a.x, a.y, a.z, a.w, b.x, b.y, b.z, b.w,
                            c4.x, c4.y, c4.z, c4.w, d.x, d.y, d.z, d.w};
            const float* wk = Ws + k * 256;
#pragma unroll
            for (int j = 0; j < 16; j++) {
                float v = fmaxf(fmaf(xv[j], rs[j], rh[j]), 0.0f);
                const float* w = wk + j * 16;
#pragma unroll
                for (int c = 0; c < 16; c++) acc[c] = fmaf(v, w[c], acc[c]);
            }
        }
    }

    if (resid) {
        const float4* rr = (const float4*)(resid + (size_t)i * 16);
#pragma unroll
        for (int q = 0; q < 4; q++) {
            float4 v = __ldg(rr + q);
            acc[4 * q + 0] += v.x; acc[4 * q + 1] += v.y;
            acc[4 * q + 2] += v.z; acc[4 * q + 3] += v.w;
        }
    }
    float4* o = (float4*)(out + (size_t)i * 16);
#pragma unroll
    for (int q = 0; q < 4; q++)
        o[q] = make_float4(acc[4 * q], acc[4 * q + 1], acc[4 * q + 2], acc[4 * q + 3]);
}

// ---------------------------------------------------------------------------
// Per-channel sum / sumsq over N rows of a [*,16] array, with optional
// gather chain (row = pB[pA[i]]) — used both for plain BN stats and for the
// duplicated-gather BN3 stats. Accumulates into g_stats[off..off+15] (sums)
// and g_stats[48+off .. 48+off+15] (sumsq).
// ---------------------------------------------------------------------------
__global__ void reduce16_kernel(const float* __restrict__ x,
                                const int* __restrict__ pA,
                                const int* __restrict__ pB,
                                int N, int off) {
    float s[16], q[16];
#pragma unroll
    for (int c = 0; c < 16; c++) { s[c] = 0.0f; q[c] = 0.0f; }

    for (int i = blockIdx.x * blockDim.x + threadIdx.x; i < N;
         i += gridDim.x * blockDim.x) {
        int r = i;
        if (pA) r = __ldg(pA + r);
        if (pB) r = __ldg(pB + r);
        const float4* xr = (const float4*)(x + (size_t)r * 16);
#pragma unroll
        for (int t = 0; t < 4; t++) {
            float4 v = __ldg(xr + t);
            s[4 * t + 0] += v.x; q[4 * t + 0] += v.x * v.x;
            s[4 * t + 1] += v.y; q[4 * t + 1] += v.y * v.y;
            s[4 * t + 2] += v.z; q[4 * t + 2] += v.z * v.z;
            s[4 * t + 3] += v.w; q[4 * t + 3] += v.w * v.w;
        }
    }

    // warp reduce
#pragma unroll
    for (int c = 0; c < 16; c++) {
#pragma unroll
        for (int o = 16; o > 0; o >>= 1) {
            s[c] += __shfl_xor_sync(0xffffffffu, s[c], o);
            q[c] += __shfl_xor_sync(0xffffffffu, q[c], o);
        }
    }
    __shared__ float ws[8][32];
    int lane = threadIdx.x & 31, wid = threadIdx.x >> 5;
    if (lane == 0) {
#pragma unroll
        for (int c = 0; c < 16; c++) { ws[wid][c] = s[c]; ws[wid][16 + c] = q[c]; }
    }
    __syncthreads();
    if (threadIdx.x < 32) {
        float v = 0.0f;
        int nw = blockDim.x >> 5;
        for (int w = 0; w < nw; w++) v += ws[w][threadIdx.x];
        int t = threadIdx.x;
        int gi = (t < 16) ? (off + t) : (48 + off + (t - 16));
        atomicAdd(&g_stats[gi], v);
    }
}

// ---------------------------------------------------------------------------
// Finalize BN: scale = g * rsqrt(var+eps), shift = b - mean*scale
// ---------------------------------------------------------------------------
__global__ void finalize_bn_kernel(const float* __restrict__ g,
                                   const float* __restrict__ b,
                                   int C, float invN) {
    int t = threadIdx.x;
    if (t < C) {
        float m = g_stats[t] * invN;
        float var = g_stats[48 + t] * invN - m * m;
        float sc = __ldg(g + t) * rsqrtf(var + EPS);
        g_scale[t] = sc;
        g_shift[t] = __ldg(b + t) - m * sc;
    }
}

// ---------------------------------------------------------------------------
// Final: fused unpool-join (3x16 gather) + BN3-ReLU + SDF linear head.
// ---------------------------------------------------------------------------
__global__ void final_out_kernel(const float* __restrict__ x0,
                                 const float* __restrict__ x1,
                                 const float* __restrict__ x2,
                                 const int* __restrict__ p01,
                                 const int* __restrict__ p12,
                                 const float* __restrict__ wsdf,
                                 const float* __restrict__ bsdf,
                                 float* __restrict__ out, int N0) {
    __shared__ float sw[48], ssc[48], ssh[48];
    if (threadIdx.x < 48) {
        sw[threadIdx.x] = __ldg(wsdf + threadIdx.x);
        ssc[threadIdx.x] = g_scale[threadIdx.x];
        ssh[threadIdx.x] = g_shift[threadIdx.x];
    }
    __syncthreads();
    int i = blockIdx.x * blockDim.x + threadIdx.x;
    if (i >= N0) return;
    int p = __ldg(p01 + i);
    int qq = __ldg(p12 + p);
    float r = __ldg(bsdf);
    const float* rows[3] = { x0 + (size_t)i * 16, x1 + (size_t)p * 16,
                             x2 + (size_t)qq * 16 };
#pragma unroll
    for (int gidx = 0; gidx < 3; gidx++) {
        const float4* xr = (const float4*)rows[gidx];
#pragma unroll
        for (int t = 0; t < 4; t++) {
            float4 v = __ldg(xr + t);
            int c = gidx * 16 + t * 4;
            r += fmaxf(fmaf(v.x, ssc[c + 0], ssh[c + 0]), 0.0f) * sw[c + 0];
            r += fmaxf(fmaf(v.y, ssc[c + 1], ssh[c + 1]), 0.0f) * sw[c + 1];
            r += fmaxf(fmaf(v.z, ssc[c + 2], ssh[c + 2]), 0.0f) * sw[c + 2];
            r += fmaxf(fmaf(v.w, ssc[c + 3], ssh[c + 3]), 0.0f) * sw[c + 3];
        }
    }
    out[i] = r;
}

// ---------------------------------------------------------------------------
// Host orchestration
// ---------------------------------------------------------------------------
static inline int gdiv(int n, int t) { return (n + t - 1) / t; }

extern "C" void kernel_launch(void* const* d_in, const int* in_sizes, int n_in,
                              void* d_out, int out_size) {
    const float* feats = (const float*)d_in[0];
    const float* w_p1  = (const float*)d_in[1];
    const float* bn1g  = (const float*)d_in[2];
    const float* bn1b  = (const float*)d_in[3];
    const float* w1    = (const float*)d_in[4];
    const float* bn2g  = (const float*)d_in[5];
    const float* bn2b  = (const float*)d_in[6];
    const float* w2    = (const float*)d_in[7];
    const float* dbng  = (const float*)d_in[8];
    const float* dbnb  = (const float*)d_in[9];
    const float* dw    = (const float*)d_in[10];
    const float* bn3g  = (const float*)d_in[11];
    const float* bn3b  = (const float*)d_in[12];
    const float* wsdf  = (const float*)d_in[13];
    const float* bsdf  = (const float*)d_in[14];
    const int* nbr0    = (const int*)d_in[15];
    const int* nbr1    = (const int*)d_in[16];
    const int* nbr2    = (const int*)d_in[17];
    const int* down01  = (const int*)d_in[18];
    const int* down12  = (const int*)d_in[19];
    const int* p01     = (const int*)d_in[20];
    const int* p12     = (const int*)d_in[21];

    int N0 = in_sizes[0] / 2;
    int N1 = in_sizes[16] / 27;
    int N2 = in_sizes[17] / 27;

    float *x0, *c0, *x1, *c1, *x2, *c2;
    cudaGetSymbolAddress((void**)&x0, g_x0);
    cudaGetSymbolAddress((void**)&c0, g_c0);
    cudaGetSymbolAddress((void**)&x1, g_x1);
    cudaGetSymbolAddress((void**)&c1, g_c1);
    cudaGetSymbolAddress((void**)&x2, g_x2);
    cudaGetSymbolAddress((void**)&c2, g_c2);

    const int T = 256;
    const int SM27 = 27 * 256 * (int)sizeof(float);
    const int SM8  = 8 * 256 * (int)sizeof(float);
    const int RG0 = (gdiv(N0, T) < 1184) ? gdiv(N0, T) : 1184;
    const int RG1 = (gdiv(N1, T) < 1184) ? gdiv(N1, T) : 1184;
    const int RG2 = (gdiv(N2, T) < 1184) ? gdiv(N2, T) : 1184;

    // ---- level 0 ----
    sconv_p1_kernel<<<gdiv(N0, T), T>>>(feats, nbr0, w_p1, x0, N0);

    zero_stats_kernel<<<1, 96>>>();
    reduce16_kernel<<<RG0, T>>>(x0, nullptr, nullptr, N0, 0);
    finalize_bn_kernel<<<1, 64>>>(bn1g + 0, bn1b + 0, 16, 1.0f / N0);
    sconv16_kernel<<<gdiv(N0, T), T, SM27>>>(x0, nbr0, w1 + 0 * 6912, nullptr, c0, 27, N0, N0);

    zero_stats_kernel<<<1, 96>>>();
    reduce16_kernel<<<RG0, T>>>(c0, nullptr, nullptr, N0, 0);
    finalize_bn_kernel<<<1, 64>>>(bn2g + 0, bn2b + 0, 16, 1.0f / N0);
    sconv16_kernel<<<gdiv(N0, T), T, SM27>>>(c0, nbr0, w2 + 0 * 6912, x0, x0, 27, N0, N0);

    zero_stats_kernel<<<1, 96>>>();
    reduce16_kernel<<<RG0, T>>>(x0, nullptr, nullptr, N0, 0);
    finalize_bn_kernel<<<1, 64>>>(dbng + 0, dbnb + 0, 16, 1.0f / N0);
    sconv16_kernel<<<gdiv(N1, T), T, SM8>>>(x0, down01, dw + 0 * 2048, nullptr, x1, 8, N1, N0);

    // ---- level 1 ----
    zero_stats_kernel<<<1, 96>>>();
    reduce16_kernel<<<RG1, T>>>(x1, nullptr, nullptr, N1, 0);
    finalize_bn_kernel<<<1, 64>>>(bn1g + 16, bn1b + 16, 16, 1.0f / N1);
    sconv16_kernel<<<gdiv(N1, T), T, SM27>>>(x1, nbr1, w1 + 1 * 6912, nullptr, c1, 27, N1, N1);

    zero_stats_kernel<<<1, 96>>>();
    reduce16_kernel<<<RG1, T>>>(c1, nullptr, nullptr, N1, 0);
    finalize_bn_kernel<<<1, 64>>>(bn2g + 16, bn2b + 16, 16, 1.0f / N1);
    sconv16_kernel<<<gdiv(N1, T), T, SM27>>>(c1, nbr1, w2 + 1 * 6912, x1, x1, 27, N1, N1);

    zero_stats_kernel<<<1, 96>>>();
    reduce16_kernel<<<RG1, T>>>(x1, nullptr, nullptr, N1, 0);
    finalize_bn_kernel<<<1, 64>>>(dbng + 16, dbnb + 16, 16, 1.0f / N1);
    sconv16_kernel<<<gdiv(N2, T), T, SM8>>>(x1, down12, dw + 1 * 2048, nullptr, x2, 8, N2, N1);

    // ---- level 2 ----
    zero_stats_kernel<<<1, 96>>>();
    reduce16_kernel<<<RG2, T>>>(x2, nullptr, nullptr, N2, 0);
    finalize_bn_kernel<<<1, 64>>>(bn1g + 32, bn1b + 32, 16, 1.0f / N2);
    sconv16_kernel<<<gdiv(N2, T), T, SM27>>>(x2, nbr2, w1 + 2 * 6912, nullptr, c2, 27, N2, N2);

    zero_stats_kernel<<<1, 96>>>();
    reduce16_kernel<<<RG2, T>>>(c2, nullptr, nullptr, N2, 0);
    finalize_bn_kernel<<<1, 64>>>(bn2g + 32, bn2b + 32, 16, 1.0f / N2);
    sconv16_kernel<<<gdiv(N2, T), T, SM27>>>(c2, nbr2, w2 + 2 * 6912, x2, x2, 27, N2, N2);

    // ---- join + BN3 + SDF head ----
    zero_stats_kernel<<<1, 96>>>();
    reduce16_kernel<<<RG0, T>>>(x0, nullptr, nullptr, N0, 0);
    reduce16_kernel<<<RG0, T>>>(x1, p01, nullptr, N0, 16);
    reduce16_kernel<<<RG0, T>>>(x2, p01, p12, N0, 32);
    finalize_bn_kernel<<<1, 64>>>(bn3g, bn3b, 48, 1.0f / N0);

    final_out_kernel<<<gdiv(N0, T), T>>>(x0, x1, x2, p01, p12, wsdf, bsdf,
                                         (float*)d_out, N0);
}

// round 2
// speedup vs baseline: 1.5164x; 1.5164x over previous
#include <cuda_runtime.h>

#define N0MAX 500000
#define EPS 1e-4f

// ---------------------------------------------------------------------------
// Scratch (device globals — no runtime allocation allowed)
// ---------------------------------------------------------------------------
__device__ float g_X0[N0MAX * 16];
__device__ float g_X1[N0MAX * 16];
__device__ float g_X2[N0MAX * 16];
__device__ float g_T1[N0MAX * 16];
__device__ float g_T2[N0MAX * 16];
// pair buffers: 3 rulebooks of K=27 + 2 of K=8, bucket stride N0MAX
__device__ int2  g_pairs[(size_t)97 * N0MAX];
__device__ int   g_cnt[5 * 32];
__device__ int   g_pfx[5 * 32];
__device__ float g_stats[96];   // sum[0..47], sumsq[48..95]
__device__ float g_scale[48];
__device__ float g_shift[48];

// rulebook bucket-base offsets into g_pairs / g_cnt
#define RB0_P ((size_t)0)
#define RB1_P ((size_t)27 * N0MAX)
#define RB2_P ((size_t)54 * N0MAX)
#define RB3_P ((size_t)81 * N0MAX)
#define RB4_P ((size_t)89 * N0MAX)

__device__ __forceinline__ void red4(float* p, float4 v) {
    asm volatile("red.global.add.v4.f32 [%0], {%1, %2, %3, %4};"
                 :: "l"(p), "f"(v.x), "f"(v.y), "f"(v.z), "f"(v.w) : "memory");
}

// ---------------------------------------------------------------------------
// Zero counters + stats (start of every call)
// ---------------------------------------------------------------------------
__global__ void zero_misc_kernel() {
    int t = threadIdx.x;
    if (t < 160) g_cnt[t] = 0;
    if (t < 96) g_stats[t] = 0.0f;
}

// ---------------------------------------------------------------------------
// Rulebook compaction: nbr [K, Nout] (sentinel == Nin) -> k-major pair lists.
// Warp-ballot slot assignment + block shared counters + one global atomic
// per (block, k). Pair order within a bucket is nondeterministic; the conv
// accumulates atomically, so the output stays within fp tolerance.
// ---------------------------------------------------------------------------
template <int K>
__global__ void compact_kernel(const int* __restrict__ nbr, int Nout, int Nin,
                               int cbase, size_t pbase) {
    __shared__ int scnt[K];
    __shared__ int sbase[K];
    if (threadIdx.x < K) scnt[threadIdx.x] = 0;
    __syncthreads();

    int i = blockIdx.x * blockDim.x + threadIdx.x;
    bool inb = i < Nout;
    int lane = threadIdx.x & 31;
    unsigned lt = (1u << lane) - 1u;

    int slotk[K], idxk[K];
#pragma unroll
    for (int k = 0; k < K; k++) {
        int idx = inb ? __ldg(nbr + (size_t)k * Nout + i) : Nin;
        bool act = idx < Nin;
        unsigned m = __ballot_sync(0xffffffffu, act);
        int lb = 0;
        if (lane == 0 && m) lb = atomicAdd(&scnt[k], __popc(m));
        lb = __shfl_sync(0xffffffffu, lb, 0);
        slotk[k] = act ? (lb + __popc(m & lt)) : -1;
        idxk[k] = idx;
    }
    __syncthreads();
    if (threadIdx.x < K)
        sbase[threadIdx.x] = atomicAdd(&g_cnt[cbase + threadIdx.x], scnt[threadIdx.x]);
    __syncthreads();
#pragma unroll
    for (int k = 0; k < K; k++)
        if (slotk[k] >= 0)
            g_pairs[pbase + (size_t)k * N0MAX + sbase[k] + slotk[k]] =
                make_int2(i, idxk[k]);
}

// prefix sums for all 5 rulebooks (tiny)
__global__ void scan_kernel() {
    if (threadIdx.x == 0) {
        for (int rb = 0; rb < 5; rb++) {
            int K = rb < 3 ? 27 : 8;
            int b = rb * 32, s = 0;
            for (int k = 0; k < K; k++) { g_pfx[b + k] = s; s += g_cnt[b + k]; }
            g_pfx[b + K] = s;
        }
    }
}

// ---------------------------------------------------------------------------
// Pair-parallel sparse conv, 16->16. One thread = one (out_i, in_idx, k) pair.
// k is warp-uniform (k-major buckets) -> W reads are broadcast LDS.128.
// Output accumulated with red.global.add.v4.f32 (out must be pre-initialized
// to zeros or the residual).
// ---------------------------------------------------------------------------
template <int K>
__global__ void pairconv16_kernel(size_t pbase, int cbase,
                                  const float* __restrict__ y,
                                  const float* __restrict__ Wg,  // [K,16,16]
                                  float* __restrict__ out) {
    __shared__ float4 Ws[K * 64];
    __shared__ int spfx[K + 1];
    for (int t = threadIdx.x; t < K * 64; t += blockDim.x)
        Ws[t] = __ldg((const float4*)Wg + t);
    if (threadIdx.x <= K) spfx[threadIdx.x] = g_pfx[cbase + threadIdx.x];
    __syncthreads();
    int P = spfx[K];

    for (int t = blockIdx.x * blockDim.x + threadIdx.x; t < P;
         t += gridDim.x * blockDim.x) {
        int lo = 0, hi = K;
        while (hi - lo > 1) {
            int mid = (lo + hi) >> 1;
            if (spfx[mid] <= t) lo = mid; else hi = mid;
        }
        int2 pr = __ldg(&g_pairs[pbase + (size_t)lo * N0MAX + (t - spfx[lo])]);
        const float4* yr = (const float4*)(y + (size_t)pr.y * 16);
        float4 y0 = __ldg(yr + 0), y1 = __ldg(yr + 1);
        float4 y2 = __ldg(yr + 2), y3 = __ldg(yr + 3);
        const float4* Wk = &Ws[lo * 64];
        float4 a0 = make_float4(0.f, 0.f, 0.f, 0.f), a1 = a0, a2 = a0, a3 = a0;

#define JSTEP(jj, yv) { \
        float4 w0 = Wk[4*(jj)+0], w1 = Wk[4*(jj)+1], w2 = Wk[4*(jj)+2], w3 = Wk[4*(jj)+3]; \
        a0.x = fmaf(yv, w0.x, a0.x); a0.y = fmaf(yv, w0.y, a0.y); \
        a0.z = fmaf(yv, w0.z, a0.z); a0.w = fmaf(yv, w0.w, a0.w); \
        a1.x = fmaf(yv, w1.x, a1.x); a1.y = fmaf(yv, w1.y, a1.y); \
        a1.z = fmaf(yv, w1.z, a1.z); a1.w = fmaf(yv, w1.w, a1.w); \
        a2.x = fmaf(yv, w2.x, a2.x); a2.y = fmaf(yv, w2.y, a2.y); \
        a2.z = fmaf(yv, w2.z, a2.z); a2.w = fmaf(yv, w2.w, a2.w); \
        a3.x = fmaf(yv, w3.x, a3.x); a3.y = fmaf(yv, w3.y, a3.y); \
        a3.z = fmaf(yv, w3.z, a3.z); a3.w = fmaf(yv, w3.w, a3.w); }

        JSTEP(0, y0.x)  JSTEP(1, y0.y)  JSTEP(2, y0.z)  JSTEP(3, y0.w)
        JSTEP(4, y1.x)  JSTEP(5, y1.y)  JSTEP(6, y1.z)  JSTEP(7, y1.w)
        JSTEP(8, y2.x)  JSTEP(9, y2.y)  JSTEP(10, y2.z) JSTEP(11, y2.w)
        JSTEP(12, y3.x) JSTEP(13, y3.y) JSTEP(14, y3.z) JSTEP(15, y3.w)
#undef JSTEP

        float* op = out + (size_t)pr.x * 16;
        red4(op + 0, a0); red4(op + 4, a1); red4(op + 8, a2); red4(op + 12, a3);
    }
}

// p1 pair conv: Cin=2 -> 16, K=27, input = raw feats (no BN)
__global__ void pairconv_p1_kernel(const float* __restrict__ feats,
                                   const float* __restrict__ Wg,  // [27,2,16]
                                   float* __restrict__ out) {
    __shared__ float4 Ws[27 * 8];
    __shared__ int spfx[28];
    for (int t = threadIdx.x; t < 27 * 8; t += blockDim.x)
        Ws[t] = __ldg((const float4*)Wg + t);
    if (threadIdx.x <= 27) spfx[threadIdx.x] = g_pfx[0 + threadIdx.x];
    __syncthreads();
    int P = spfx[27];

    for (int t = blockIdx.x * blockDim.x + threadIdx.x; t < P;
         t += gridDim.x * blockDim.x) {
        int lo = 0, hi = 27;
        while (hi - lo > 1) {
            int mid = (lo + hi) >> 1;
            if (spfx[mid] <= t) lo = mid; else hi = mid;
        }
        int2 pr = __ldg(&g_pairs[RB0_P + (size_t)lo * N0MAX + (t - spfx[lo])]);
        float2 f = __ldg((const float2*)(feats + (size_t)pr.y * 2));
        const float4* Wk = &Ws[lo * 8];
        float4 a0, a1, a2, a3;
        {
            float4 u0 = Wk[0], u1 = Wk[1], u2 = Wk[2], u3 = Wk[3];
            float4 v0 = Wk[4], v1 = Wk[5], v2 = Wk[6], v3 = Wk[7];
            a0 = make_float4(fmaf(f.y, v0.x, f.x * u0.x), fmaf(f.y, v0.y, f.x * u0.y),
                             fmaf(f.y, v0.z, f.x * u0.z), fmaf(f.y, v0.w, f.x * u0.w));
            a1 = make_float4(fmaf(f.y, v1.x, f.x * u1.x), fmaf(f.y, v1.y, f.x * u1.y),
                             fmaf(f.y, v1.z, f.x * u1.z), fmaf(f.y, v1.w, f.x * u1.w));
            a2 = make_float4(fmaf(f.y, v2.x, f.x * u2.x), fmaf(f.y, v2.y, f.x * u2.y),
                             fmaf(f.y, v2.z, f.x * u2.z), fmaf(f.y, v2.w, f.x * u2.w));
            a3 = make_float4(fmaf(f.y, v3.x, f.x * u3.x), fmaf(f.y, v3.y, f.x * u3.y),
                             fmaf(f.y, v3.z, f.x * u3.z), fmaf(f.y, v3.w, f.x * u3.w));
        }
        float* op = out + (size_t)pr.x * 16;
        red4(op + 0, a0); red4(op + 4, a1); red4(op + 8, a2); red4(op + 12, a3);
    }
}

// ---------------------------------------------------------------------------
// y = relu(x*scale+shift) elementwise; optionally zero-initialize zb[Nz rows]
// (the next conv's red-accumulation target) in the same pass.
// ---------------------------------------------------------------------------
__global__ void bnrelu_zero_kernel(const float* __restrict__ x,
                                   float* __restrict__ y,
                                   float* __restrict__ zb, int N, int Nz) {
    int i = blockIdx.x * blockDim.x + threadIdx.x;
    if (i < N) {
        const float4* xr = (const float4*)(x + (size_t)i * 16);
        float4* yr = (float4*)(y + (size_t)i * 16);
#pragma unroll
        for (int q = 0; q < 4; q++) {
            float4 v = __ldg(xr + q);
            v.x = fmaxf(fmaf(v.x, g_scale[4 * q + 0], g_shift[4 * q + 0]), 0.f);
            v.y = fmaxf(fmaf(v.y, g_scale[4 * q + 1], g_shift[4 * q + 1]), 0.f);
            v.z = fmaxf(fmaf(v.z, g_scale[4 * q + 2], g_shift[4 * q + 2]), 0.f);
            v.w = fmaxf(fmaf(v.w, g_scale[4 * q + 3], g_shift[4 * q + 3]), 0.f);
            yr[q] = v;
        }
    }
    if (zb != nullptr && i < Nz) {
        float4* zr = (float4*)(zb + (size_t)i * 16);
        float4 z = make_float4(0.f, 0.f, 0.f, 0.f);
        zr[0] = z; zr[1] = z; zr[2] = z; zr[3] = z;
    }
}

// ---------------------------------------------------------------------------
// Per-channel sum / sumsq over N rows, optional gather chain row=pB[pA[i]].
// ---------------------------------------------------------------------------
__global__ void reduce16_kernel(const float* __restrict__ x,
                                const int* __restrict__ pA,
                                const int* __restrict__ pB,
                                int N, int off) {
    float s[16], q[16];
#pragma unroll
    for (int c = 0; c < 16; c++) { s[c] = 0.0f; q[c] = 0.0f; }

    for (int i = blockIdx.x * blockDim.x + threadIdx.x; i < N;
         i += gridDim.x * blockDim.x) {
        int r = i;
        if (pA) r = __ldg(pA + r);
        if (pB) r = __ldg(pB + r);
        const float4* xr = (const float4*)(x + (size_t)r * 16);
#pragma unroll
        for (int t = 0; t < 4; t++) {
            float4 v = __ldg(xr + t);
            s[4 * t + 0] += v.x; q[4 * t + 0] += v.x * v.x;
            s[4 * t + 1] += v.y; q[4 * t + 1] += v.y * v.y;
            s[4 * t + 2] += v.z; q[4 * t + 2] += v.z * v.z;
            s[4 * t + 3] += v.w; q[4 * t + 3] += v.w * v.w;
        }
    }
#pragma unroll
    for (int c = 0; c < 16; c++) {
#pragma unroll
        for (int o = 16; o > 0; o >>= 1) {
            s[c] += __shfl_xor_sync(0xffffffffu, s[c], o);
            q[c] += __shfl_xor_sync(0xffffffffu, q[c], o);
        }
    }
    __shared__ float ws[8][32];
    int lane = threadIdx.x & 31, wid = threadIdx.x >> 5;
    if (lane == 0) {
#pragma unroll
        for (int c = 0; c < 16; c++) { ws[wid][c] = s[c]; ws[wid][16 + c] = q[c]; }
    }
    __syncthreads();
    if (threadIdx.x < 32) {
        float v = 0.0f;
        int nw = blockDim.x >> 5;
        for (int w = 0; w < nw; w++) v += ws[w][threadIdx.x];
        int t = threadIdx.x;
        int gi = (t < 16) ? (off + t) : (48 + off + (t - 16));
        atomicAdd(&g_stats[gi], v);
    }
}

// finalize BN and reset the stats slots it consumed (for the next use)
__global__ void finalize_bn_kernel(const float* __restrict__ g,
                                   const float* __restrict__ b,
                                   int C, float invN) {
    int t = threadIdx.x;
    if (t < C) {
        float m = g_stats[t] * invN;
        float var = g_stats[48 + t] * invN - m * m;
        float sc = __ldg(g + t) * rsqrtf(var + EPS);
        g_scale[t] = sc;
        g_shift[t] = __ldg(b + t) - m * sc;
        g_stats[t] = 0.0f;
        g_stats[48 + t] = 0.0f;
    }
}

// ---------------------------------------------------------------------------
// Final: fused unpool-join (3x16 gather) + BN3-ReLU + SDF linear head.
// ---------------------------------------------------------------------------
__global__ void final_out_kernel(const float* __restrict__ x0,
                                 const float* __restrict__ x1,
                                 const float* __restrict__ x2,
                                 const int* __restrict__ p01,
                                 const int* __restrict__ p12,
                                 const float* __restrict__ wsdf,
                                 const float* __restrict__ bsdf,
                                 float* __restrict__ out, int N0) {
    __shared__ float sw[48], ssc[48], ssh[48];
    if (threadIdx.x < 48) {
        sw[threadIdx.x] = __ldg(wsdf + threadIdx.x);
        ssc[threadIdx.x] = g_scale[threadIdx.x];
        ssh[threadIdx.x] = g_shift[threadIdx.x];
    }
    __syncthreads();
    int i = blockIdx.x * blockDim.x + threadIdx.x;
    if (i >= N0) return;
    int p = __ldg(p01 + i);
    int qq = __ldg(p12 + p);
    float r = __ldg(bsdf);
    const float* rows[3] = { x0 + (size_t)i * 16, x1 + (size_t)p * 16,
                             x2 + (size_t)qq * 16 };
#pragma unroll
    for (int gidx = 0; gidx < 3; gidx++) {
        const float4* xr = (const float4*)rows[gidx];
#pragma unroll
        for (int t = 0; t < 4; t++) {
            float4 v = __ldg(xr + t);
            int c = gidx * 16 + t * 4;
            r += fmaxf(fmaf(v.x, ssc[c + 0], ssh[c + 0]), 0.0f) * sw[c + 0];
            r += fmaxf(fmaf(v.y, ssc[c + 1], ssh[c + 1]), 0.0f) * sw[c + 1];
            r += fmaxf(fmaf(v.z, ssc[c + 2], ssh[c + 2]), 0.0f) * sw[c + 2];
            r += fmaxf(fmaf(v.w, ssc[c + 3], ssh[c + 3]), 0.0f) * sw[c + 3];
        }
    }
    out[i] = r;
}

// ---------------------------------------------------------------------------
// Host orchestration
// ---------------------------------------------------------------------------
static inline int gdiv(int n, int t) { return (n + t - 1) / t; }

extern "C" void kernel_launch(void* const* d_in, const int* in_sizes, int n_in,
                              void* d_out, int out_size) {
    const float* feats = (const float*)d_in[0];
    const float* w_p1  = (const float*)d_in[1];
    const float* bn1g  = (const float*)d_in[2];
    const float* bn1b  = (const float*)d_in[3];
    const float* w1    = (const float*)d_in[4];
    const float* bn2g  = (const float*)d_in[5];
    const float* bn2b  = (const float*)d_in[6];
    const float* w2    = (const float*)d_in[7];
    const float* dbng  = (const float*)d_in[8];
    const float* dbnb  = (const float*)d_in[9];
    const float* dw    = (const float*)d_in[10];
    const float* bn3g  = (const float*)d_in[11];
    const float* bn3b  = (const float*)d_in[12];
    const float* wsdf  = (const float*)d_in[13];
    const float* bsdf  = (const float*)d_in[14];
    const int* nbr0    = (const int*)d_in[15];
    const int* nbr1    = (const int*)d_in[16];
    const int* nbr2    = (const int*)d_in[17];
    const int* down01  = (const int*)d_in[18];
    const int* down12  = (const int*)d_in[19];
    const int* p01     = (const int*)d_in[20];
    const int* p12     = (const int*)d_in[21];

    int N0 = in_sizes[0] / 2;
    int N1 = in_sizes[16] / 27;
    int N2 = in_sizes[17] / 27;

    float *X0, *X1, *X2, *T1, *T2;
    cudaGetSymbolAddress((void**)&X0, g_X0);
    cudaGetSymbolAddress((void**)&X1, g_X1);
    cudaGetSymbolAddress((void**)&X2, g_X2);
    cudaGetSymbolAddress((void**)&T1, g_T1);
    cudaGetSymbolAddress((void**)&T2, g_T2);

    const int T = 256;
    const int PG = 1184;   // persistent-ish grid for pair convs (grid-stride)
    const int RG0 = (gdiv(N0, T) < 1184) ? gdiv(N0, T) : 1184;
    const int RG1 = (gdiv(N1, T) < 1184) ? gdiv(N1, T) : 1184;
    const int RG2 = (gdiv(N2, T) < 1184) ? gdiv(N2, T) : 1184;

    // ---- compaction of all 5 rulebooks ----
    zero_misc_kernel<<<1, 256>>>();
    compact_kernel<27><<<gdiv(N0, 128), 128>>>(nbr0, N0, N0, 0,   RB0_P);
    compact_kernel<27><<<gdiv(N1, 128), 128>>>(nbr1, N1, N1, 32,  RB1_P);
    compact_kernel<27><<<gdiv(N2, 128), 128>>>(nbr2, N2, N2, 64,  RB2_P);
    compact_kernel<8> <<<gdiv(N1, 128), 128>>>(down01, N1, N0, 96, RB3_P);
    compact_kernel<8> <<<gdiv(N2, 128), 128>>>(down12, N2, N1, 128, RB4_P);
    scan_kernel<<<1, 32>>>();

    // ---- level 0 ----
    cudaMemsetAsync(X0, 0, (size_t)N0 * 16 * sizeof(float), 0);
    pairconv_p1_kernel<<<PG, T>>>(feats, w_p1, X0);                     // X0 = x

    reduce16_kernel<<<RG0, T>>>(X0, nullptr, nullptr, N0, 0);
    finalize_bn_kernel<<<1, 64>>>(bn1g + 0, bn1b + 0, 16, 1.0f / N0);
    bnrelu_zero_kernel<<<gdiv(N0, T), T>>>(X0, T1, T2, N0, N0);
    pairconv16_kernel<27><<<PG, T>>>(RB0_P, 0, T1, w1 + 0 * 6912, T2);  // T2 = h1

    reduce16_kernel<<<RG0, T>>>(T2, nullptr, nullptr, N0, 0);
    finalize_bn_kernel<<<1, 64>>>(bn2g + 0, bn2b + 0, 16, 1.0f / N0);
    bnrelu_zero_kernel<<<gdiv(N0, T), T>>>(T2, T1, nullptr, N0, 0);
    pairconv16_kernel<27><<<PG, T>>>(RB0_P, 0, T1, w2 + 0 * 6912, X0);  // X0 = r0

    reduce16_kernel<<<RG0, T>>>(X0, nullptr, nullptr, N0, 0);
    finalize_bn_kernel<<<1, 64>>>(dbng + 0, dbnb + 0, 16, 1.0f / N0);
    bnrelu_zero_kernel<<<gdiv(N0, T), T>>>(X0, T1, X1, N0, N1);
    pairconv16_kernel<8><<<PG, T>>>(RB3_P, 96, T1, dw + 0 * 2048, X1);  // X1 = y1

    // ---- level 1 ----
    reduce16_kernel<<<RG1, T>>>(X1, nullptr, nullptr, N1, 0);
    finalize_bn_kernel<<<1, 64>>>(bn1g + 16, bn1b + 16, 16, 1.0f / N1);
    bnrelu_zero_kernel<<<gdiv(N1, T), T>>>(X1, T1, T2, N1, N1);
    pairconv16_kernel<27><<<PG, T>>>(RB1_P, 32, T1, w1 + 1 * 6912, T2);

    reduce16_kernel<<<RG1, T>>>(T2, nullptr, nullptr, N1, 0);
    finalize_bn_kernel<<<1, 64>>>(bn2g + 16, bn2b + 16, 16, 1.0f / N1);
    bnrelu_zero_kernel<<<gdiv(N1, T), T>>>(T2, T1, nullptr, N1, 0);
    pairconv16_kernel<27><<<PG, T>>>(RB1_P, 32, T1, w2 + 1 * 6912, X1); // X1 = r1

    reduce16_kernel<<<RG1, T>>>(X1, nullptr, nullptr, N1, 0);
    finalize_bn_kernel<<<1, 64>>>(dbng + 16, dbnb + 16, 16, 1.0f / N1);
    bnrelu_zero_kernel<<<gdiv(N1, T), T>>>(X1, T1, X2, N1, N2);
    pairconv16_kernel<8><<<PG, T>>>(RB4_P, 128, T1, dw + 1 * 2048, X2); // X2 = z2

    // ---- level 2 ----
    reduce16_kernel<<<RG2, T>>>(X2, nullptr, nullptr, N2, 0);
    finalize_bn_kernel<<<1, 64>>>(bn1g + 32, bn1b + 32, 16, 1.0f / N2);
    bnrelu_zero_kernel<<<gdiv(N2, T), T>>>(X2, T1, T2, N2, N2);
    pairconv16_kernel<27><<<PG, T>>>(RB2_P, 64, T1, w1 + 2 * 6912, T2);

    reduce16_kernel<<<RG2, T>>>(T2, nullptr, nullptr, N2, 0);
    finalize_bn_kernel<<<1, 64>>>(bn2g + 32, bn2b + 32, 16, 1.0f / N2);
    bnrelu_zero_kernel<<<gdiv(N2, T), T>>>(T2, T1, nullptr, N2, 0);
    pairconv16_kernel<27><<<PG, T>>>(RB2_P, 64, T1, w2 + 2 * 6912, X2); // X2 = r2

    // ---- join + BN3 + SDF head ----
    reduce16_kernel<<<RG0, T>>>(X0, nullptr, nullptr, N0, 0);
    reduce16_kernel<<<RG0, T>>>(X1, p01, nullptr, N0, 16);
    reduce16_kernel<<<RG0, T>>>(X2, p01, p12, N0, 32);
    finalize_bn_kernel<<<1, 64>>>(bn3g, bn3b, 48, 1.0f / N0);

    final_out_kernel<<<gdiv(N0, T), T>>>(X0, X1, X2, p01, p12, wsdf, bsdf,
                                         (float*)d_out, N0);
}